// round 11
// baseline (speedup 1.0000x reference)
#include <cuda_runtime.h>
#include <cuda_bf16.h>
#include <math.h>
#include <stdint.h>

#define BATCH   16
#define CH      512
#define HW_     1024
#define NGROUPS 8
#define CG      64
#define NH      8
#define HD      64
#define EPS_    1e-5f
#define SCALE_  0.125f

// Scratch (allocation-free)
__device__ __nv_bfloat16 g_xn [BATCH*CH*HW_];
__device__ __nv_bfloat16 g_qkv[(size_t)BATCH*3*CH*HW_];
__device__ __nv_bfloat16 g_att[BATCH*CH*HW_];
__device__ __nv_bfloat16 g_wq [3*CH*CH];
__device__ __nv_bfloat16 g_wp [CH*CH];

// ---------------------------------------------------------------------------
// helpers
// ---------------------------------------------------------------------------
__device__ __forceinline__ uint32_t sptr(const void* p) {
    return (uint32_t)__cvta_generic_to_shared(p);
}
__device__ __forceinline__ uint32_t packbf(float a, float b) {
    __nv_bfloat162 t = __float22bfloat162_rn(make_float2(a, b));
    return *(uint32_t*)&t;
}
__device__ __forceinline__ void cpa16(uint32_t s, const void* g) {
    asm volatile("cp.async.cg.shared.global [%0],[%1],16;" :: "r"(s), "l"(g));
}
#define CP_COMMIT() asm volatile("cp.async.commit_group;")
#define CP_WAIT(n)  asm volatile("cp.async.wait_group %0;" :: "n"(n))

__device__ __forceinline__ void ldsm4(uint32_t* r, uint32_t a) {
    asm volatile("ldmatrix.sync.aligned.m8n8.x4.shared.b16 {%0,%1,%2,%3},[%4];"
        : "=r"(r[0]), "=r"(r[1]), "=r"(r[2]), "=r"(r[3]) : "r"(a));
}
__device__ __forceinline__ void ldsm4t(uint32_t* r, uint32_t a) {
    asm volatile("ldmatrix.sync.aligned.m8n8.x4.trans.shared.b16 {%0,%1,%2,%3},[%4];"
        : "=r"(r[0]), "=r"(r[1]), "=r"(r[2]), "=r"(r[3]) : "r"(a));
}
__device__ __forceinline__ void mma_bf16(float* c, const uint32_t* a, const uint32_t* b) {
    asm volatile("mma.sync.aligned.m16n8k16.row.col.f32.bf16.bf16.f32 "
        "{%0,%1,%2,%3},{%4,%5,%6,%7},{%8,%9},{%0,%1,%2,%3};"
        : "+f"(c[0]), "+f"(c[1]), "+f"(c[2]), "+f"(c[3])
        : "r"(a[0]), "r"(a[1]), "r"(a[2]), "r"(a[3]), "r"(b[0]), "r"(b[1]));
}

// ---------------------------------------------------------------------------
// fp32 -> bf16 weight conversion
// ---------------------------------------------------------------------------
__global__ void f2bf_kernel(const float* __restrict__ src,
                            __nv_bfloat16* __restrict__ dst, int n)
{
    int i = (blockIdx.x*blockDim.x + threadIdx.x) * 4;
    if (i < n) {
        float4 v = *(const float4*)&src[i];
        uint2 o;
        o.x = packbf(v.x, v.y);
        o.y = packbf(v.z, v.w);
        *(uint2*)&dst[i] = o;
    }
}

// ---------------------------------------------------------------------------
// GroupNorm -> bf16
// ---------------------------------------------------------------------------
__global__ void groupnorm_kernel(const float* __restrict__ x,
                                 const float* __restrict__ w,
                                 const float* __restrict__ bias,
                                 __nv_bfloat16* __restrict__ xn)
{
    int bg = blockIdx.x;
    int bb = bg / NGROUPS, g = bg % NGROUPS;
    const float*   xp = x  + ((size_t)bb*CH + g*CG) * HW_;
    __nv_bfloat16* op = xn + ((size_t)bb*CH + g*CG) * HW_;
    const int NEL = CG * HW_;
    int tid = threadIdx.x;

    float s = 0.f, ss = 0.f;
    for (int i = tid*4; i < NEL; i += blockDim.x*4) {
        float4 v = *(const float4*)&xp[i];
        s  += v.x + v.y + v.z + v.w;
        ss += v.x*v.x + v.y*v.y + v.z*v.z + v.w*v.w;
    }
    __shared__ float r1[1024], r2[1024];
    r1[tid] = s; r2[tid] = ss;
    __syncthreads();
    for (int st = 512; st > 0; st >>= 1) {
        if (tid < st) { r1[tid] += r1[tid+st]; r2[tid] += r2[tid+st]; }
        __syncthreads();
    }
    float mean = r1[0] * (1.f/NEL);
    float var  = r2[0] * (1.f/NEL) - mean*mean;
    float inv  = rsqrtf(var + EPS_);

    for (int i = tid*4; i < NEL; i += blockDim.x*4) {
        int ch = g*CG + (i >> 10);
        float wc = w[ch], bc = bias[ch];
        float4 v = *(const float4*)&xp[i];
        uint2 o;
        o.x = packbf((v.x - mean)*inv*wc + bc, (v.y - mean)*inv*wc + bc);
        o.y = packbf((v.z - mean)*inv*wc + bc, (v.w - mean)*inv*wc + bc);
        *(uint2*)&op[i] = o;
    }
}

// ---------------------------------------------------------------------------
// bf16 MMA GEMM, 4-stage cp.async pipeline, single sync per K-iteration,
// prefetch issued BEFORE the MMA block. 128x128x32, 8 warps (2x4).
// ---------------------------------------------------------------------------
#define GBM 128
#define GBN 128
#define GBK 32
#define ASTR 40
#define BSTR 136
#define A_ST (GBM*ASTR)
#define B_ST (GBK*BSTR)
#define GEMM_SMEM ((4*A_ST + 4*B_ST) * 2)   // 75776 B

template<bool OUT_BF16>
__global__ __launch_bounds__(256)
void mma_gemm_kernel(const __nv_bfloat16* __restrict__ A,
                     const __nv_bfloat16* __restrict__ Bbase,
                     void* __restrict__ Cbase,
                     const float* __restrict__ bias,
                     const float* __restrict__ Rbase,
                     int M, int K, int N, int q_rows)
{
    extern __shared__ __align__(16) uint16_t smg[];
    uint16_t* As = smg;              // [4][128*40]
    uint16_t* Bs = smg + 4*A_ST;     // [4][32*136]

    int bz = blockIdx.z;
    const __nv_bfloat16* Bm = Bbase + (size_t)bz * K * N;

    int m0 = blockIdx.y * GBM, n0 = blockIdx.x * GBN;
    int tid = threadIdx.x, lane = tid & 31, warp = tid >> 5;
    int wm = (warp >> 2) * 64, wn = (warp & 3) * 32;

    int arow = tid >> 1, acol = (tid & 1) * 16;
    int brow = tid >> 3, bcol = (tid & 7) * 16;

    const __nv_bfloat16* Ab = A + (size_t)(m0 + arow)*K + acol;
    const __nv_bfloat16* Bb = Bm + (size_t)brow*N + n0 + bcol;

    float c[4][4][4];
    #pragma unroll
    for (int mt = 0; mt < 4; mt++)
        #pragma unroll
        for (int nt = 0; nt < 4; nt++)
            #pragma unroll
            for (int e = 0; e < 4; e++) c[mt][nt][e] = 0.f;

    const int KT = K / GBK;

    // prologue: 3 stages in flight
    #pragma unroll
    for (int p = 0; p < 3; p++) {
        int st = p, k0 = p * GBK;
        cpa16(sptr(&As[st*A_ST + arow*ASTR + acol]),     Ab + k0);
        cpa16(sptr(&As[st*A_ST + arow*ASTR + acol + 8]), Ab + k0 + 8);
        cpa16(sptr(&Bs[st*B_ST + brow*BSTR + bcol]),     Bb + (size_t)k0*N);
        cpa16(sptr(&Bs[st*B_ST + brow*BSTR + bcol + 8]), Bb + (size_t)k0*N + 8);
        CP_COMMIT();
    }

    for (int kt = 0; kt < KT; kt++) {
        CP_WAIT(2);            // group kt complete
        __syncthreads();

        // issue stage kt+3 NOW (writes buf (kt-1)%4: all reads finished before
        // the barrier above) so DMA overlaps the whole MMA block below.
        if (kt + 3 < KT) {
            int st = (kt + 3) & 3, k0 = (kt + 3) * GBK;
            cpa16(sptr(&As[st*A_ST + arow*ASTR + acol]),     Ab + k0);
            cpa16(sptr(&As[st*A_ST + arow*ASTR + acol + 8]), Ab + k0 + 8);
            cpa16(sptr(&Bs[st*B_ST + brow*BSTR + bcol]),     Bb + (size_t)k0*N);
            cpa16(sptr(&Bs[st*B_ST + brow*BSTR + bcol + 8]), Bb + (size_t)k0*N + 8);
        }
        CP_COMMIT();

        const uint16_t* Ac = As + (kt & 3)*A_ST;
        const uint16_t* Bc = Bs + (kt & 3)*B_ST;

        #pragma unroll
        for (int ks = 0; ks < 2; ks++) {
            uint32_t a[4][4], b[2][4];
            int g = lane >> 3;
            #pragma unroll
            for (int mt = 0; mt < 4; mt++) {
                int row = wm + mt*16 + (g & 1)*8 + (lane & 7);
                int col = ks*16 + (g >> 1)*8;
                ldsm4(a[mt], sptr(&Ac[row*ASTR + col]));
            }
            int kk = ks*16 + (lane & 15);
            int cb = (lane >> 4)*8;
            ldsm4t(b[0], sptr(&Bc[kk*BSTR + wn + cb]));
            ldsm4t(b[1], sptr(&Bc[kk*BSTR + wn + 16 + cb]));
            #pragma unroll
            for (int mt = 0; mt < 4; mt++)
                #pragma unroll
                for (int ntp = 0; ntp < 2; ntp++) {
                    mma_bf16(c[mt][2*ntp],   a[mt], &b[ntp][0]);
                    mma_bf16(c[mt][2*ntp+1], a[mt], &b[ntp][2]);
                }
        }
    }

    #pragma unroll
    for (int mt = 0; mt < 4; mt++) {
        #pragma unroll
        for (int half = 0; half < 2; half++) {
            int m = m0 + wm + mt*16 + (lane >> 2) + half*8;
            float bv = bias ? bias[m] : 0.f;
            #pragma unroll
            for (int nt = 0; nt < 4; nt++) {
                int n = n0 + wn + nt*8 + 2*(lane & 3);
                float x0 = c[mt][nt][half*2 + 0] + bv;
                float x1 = c[mt][nt][half*2 + 1] + bv;
                if (OUT_BF16) {
                    float sc = (m < q_rows) ? SCALE_ : 1.0f;
                    *(uint32_t*)((__nv_bfloat16*)Cbase + (size_t)bz*M*N + (size_t)m*N + n)
                        = packbf(x0*sc, x1*sc);
                } else {
                    float2 o = make_float2(x0, x1);
                    if (Rbase) {
                        float2 r = *(const float2*)&Rbase[(size_t)bz*M*N + (size_t)m*N + n];
                        o.x += r.x; o.y += r.y;
                    }
                    *(float2*)((float*)Cbase + (size_t)bz*M*N + (size_t)m*N + n) = o;
                }
            }
        }
    }
}

// ---------------------------------------------------------------------------
// Flash attention: 128 queries/block, 8 warps (one 16-row q-tile per warp),
// 3-stage cp.async KV pipeline, prefetch before compute, P in registers.
// launch_bounds(256,2) -> 16 warps/SM.
// ---------------------------------------------------------------------------
#define KSTR 72
#define QSTR2 136
#define OFF_KS (64*QSTR2)                      // after Qs
#define OFF_VS (OFF_KS + 3*64*KSTR)
#define ATT_SMEM_HALVES (OFF_VS + 3*64*KSTR)   // 36352
#define ATT_SMEM (ATT_SMEM_HALVES * 2)         // 72704 B

__global__ __launch_bounds__(256, 2)
void attention_kernel(const __nv_bfloat16* __restrict__ qkv,
                      __nv_bfloat16* __restrict__ outp)
{
    extern __shared__ __align__(16) uint16_t sm[];
    uint16_t* Qs = sm;            // [64][136] — Q stage, then O stage
    uint16_t* Ks = sm + OFF_KS;   // [3][64][72]
    uint16_t* Vs = sm + OFF_VS;   // [3][64][72]

    int bh = blockIdx.y;
    int bb = bh >> 3, hh = bh & 7;
    int i0 = blockIdx.x * 128;
    const __nv_bfloat16* qp = qkv + ((size_t)bb*3*CH + hh*HD) * HW_;
    const __nv_bfloat16* kp = qp + (size_t)CH * HW_;
    const __nv_bfloat16* vp = qp + (size_t)2*CH * HW_;

    int tid = threadIdx.x, lane = tid & 31, warp = tid >> 5;

    // prologue: group0 = Q + KV tile 0; group1 = KV tile 1
    #pragma unroll
    for (int r = 0; r < 4; r++) {
        int idx = r*256 + tid;
        int d = idx >> 4, cc = (idx & 15) * 8;
        cpa16(sptr(&Qs[d*QSTR2 + cc]), qp + (size_t)d*HW_ + i0 + cc);
    }
    #pragma unroll
    for (int r = 0; r < 2; r++) {
        int idx = r*256 + tid;
        int d = idx >> 3, cc = (idx & 7) * 8;
        cpa16(sptr(&Ks[d*KSTR + cc]), kp + (size_t)d*HW_ + cc);
        cpa16(sptr(&Vs[d*KSTR + cc]), vp + (size_t)d*HW_ + cc);
    }
    CP_COMMIT();
    #pragma unroll
    for (int r = 0; r < 2; r++) {
        int idx = r*256 + tid;
        int d = idx >> 3, cc = (idx & 7) * 8;
        cpa16(sptr(&Ks[64*KSTR + d*KSTR + cc]), kp + (size_t)d*HW_ + 64 + cc);
        cpa16(sptr(&Vs[64*KSTR + d*KSTR + cc]), vp + (size_t)d*HW_ + 64 + cc);
    }
    CP_COMMIT();

    uint32_t qf[4][4];
    float mx0 = -1e30f, mx1 = -1e30f, l0 = 0.f, l1 = 0.f;
    float o[8][4];
    #pragma unroll
    for (int nt = 0; nt < 8; nt++)
        #pragma unroll
        for (int e = 0; e < 4; e++) o[nt][e] = 0.f;

    for (int jt = 0; jt < 16; jt++) {
        CP_WAIT(1);
        __syncthreads();

        // issue KV tile jt+2 NOW (stage (jt-1)%3: readers finished pre-barrier)
        if (jt + 2 < 16) {
            int stp = (jt + 2) % 3;
            int j0 = (jt + 2) * 64;
            #pragma unroll
            for (int r = 0; r < 2; r++) {
                int idx = r*256 + tid;
                int d = idx >> 3, cc = (idx & 7) * 8;
                cpa16(sptr(&Ks[stp*64*KSTR + d*KSTR + cc]), kp + (size_t)d*HW_ + j0 + cc);
                cpa16(sptr(&Vs[stp*64*KSTR + d*KSTR + cc]), vp + (size_t)d*HW_ + j0 + cc);
            }
        }
        CP_COMMIT();

        if (jt == 0) {   // Q frags (register-resident afterwards)
            int g = lane >> 3;
            int kq = (g >> 1)*8 + (lane & 7);
            int mq = warp*16 + (g & 1)*8;
            #pragma unroll
            for (int ks = 0; ks < 4; ks++)
                ldsm4t(qf[ks], sptr(&Qs[(ks*16 + kq)*QSTR2 + mq]));
        }

        const uint16_t* Kc = Ks + (jt % 3)*64*KSTR;
        const uint16_t* Vc = Vs + (jt % 3)*64*KSTR;

        // S = Q K^T  (warp's 16 rows x 64 keys)
        float s[8][4];
        #pragma unroll
        for (int nt = 0; nt < 8; nt++)
            #pragma unroll
            for (int e = 0; e < 4; e++) s[nt][e] = 0.f;

        #pragma unroll
        for (int ks = 0; ks < 4; ks++) {
            int kk = ks*16 + (lane & 15);
            int cb = (lane >> 4)*8;
            #pragma unroll
            for (int ntp = 0; ntp < 4; ntp++) {
                uint32_t b[4];
                ldsm4t(b, sptr(&Kc[kk*KSTR + ntp*16 + cb]));
                mma_bf16(s[2*ntp],   qf[ks], &b[0]);
                mma_bf16(s[2*ntp+1], qf[ks], &b[2]);
            }
        }

        // online softmax (rows r0 = warp*16 + lane/4, r1 = r0+8)
        float rmax0 = -1e30f, rmax1 = -1e30f;
        #pragma unroll
        for (int nt = 0; nt < 8; nt++) {
            rmax0 = fmaxf(rmax0, fmaxf(s[nt][0], s[nt][1]));
            rmax1 = fmaxf(rmax1, fmaxf(s[nt][2], s[nt][3]));
        }
        #pragma unroll
        for (int off = 1; off < 4; off <<= 1) {
            rmax0 = fmaxf(rmax0, __shfl_xor_sync(0xffffffffu, rmax0, off));
            rmax1 = fmaxf(rmax1, __shfl_xor_sync(0xffffffffu, rmax1, off));
        }
        float mn0 = fmaxf(mx0, rmax0), mn1 = fmaxf(mx1, rmax1);
        float corr0 = __expf(mx0 - mn0), corr1 = __expf(mx1 - mn1);
        mx0 = mn0; mx1 = mn1;

        float rs0 = 0.f, rs1 = 0.f;
        #pragma unroll
        for (int nt = 0; nt < 8; nt++) {
            s[nt][0] = __expf(s[nt][0] - mn0);
            s[nt][1] = __expf(s[nt][1] - mn0);
            s[nt][2] = __expf(s[nt][2] - mn1);
            s[nt][3] = __expf(s[nt][3] - mn1);
            rs0 += s[nt][0] + s[nt][1];
            rs1 += s[nt][2] + s[nt][3];
        }
        #pragma unroll
        for (int off = 1; off < 4; off <<= 1) {
            rs0 += __shfl_xor_sync(0xffffffffu, rs0, off);
            rs1 += __shfl_xor_sync(0xffffffffu, rs1, off);
        }
        l0 = l0*corr0 + rs0;
        l1 = l1*corr1 + rs1;
        #pragma unroll
        for (int nt = 0; nt < 8; nt++) {
            o[nt][0] *= corr0; o[nt][1] *= corr0;
            o[nt][2] *= corr1; o[nt][3] *= corr1;
        }

        // O += P @ V — P A-frags straight from S C-frags
        #pragma unroll
        for (int ks = 0; ks < 4; ks++) {
            uint32_t pa[4];
            pa[0] = packbf(s[2*ks][0],   s[2*ks][1]);
            pa[1] = packbf(s[2*ks][2],   s[2*ks][3]);
            pa[2] = packbf(s[2*ks+1][0], s[2*ks+1][1]);
            pa[3] = packbf(s[2*ks+1][2], s[2*ks+1][3]);
            int jc = ks*16 + ((lane >> 3) & 1)*8;
            int dbase = (lane >> 4)*8 + (lane & 7);
            #pragma unroll
            for (int ntp = 0; ntp < 4; ntp++) {
                uint32_t b[4];
                ldsm4(b, sptr(&Vc[(ntp*16 + dbase)*KSTR + jc]));
                mma_bf16(o[2*ntp],   pa, &b[0]);
                mma_bf16(o[2*ntp+1], pa, &b[2]);
            }
        }
    }

    // normalize + stage O as bf16 [d][i] into Qs (Q long consumed)
    __syncthreads();
    {
        __nv_bfloat16* Od = (__nv_bfloat16*)Qs;
        float inv0 = 1.f / l0, inv1 = 1.f / l1;
        int iq = warp*16 + (lane >> 2);
        #pragma unroll
        for (int nt = 0; nt < 8; nt++) {
            int d = nt*8 + 2*(lane & 3);
            Od[(size_t)d*QSTR2 + iq]         = __float2bfloat16_rn(o[nt][0]*inv0);
            Od[(size_t)(d+1)*QSTR2 + iq]     = __float2bfloat16_rn(o[nt][1]*inv0);
            Od[(size_t)d*QSTR2 + iq + 8]     = __float2bfloat16_rn(o[nt][2]*inv1);
            Od[(size_t)(d+1)*QSTR2 + iq + 8] = __float2bfloat16_rn(o[nt][3]*inv1);
        }
    }
    __syncthreads();

    // coalesced store out[d][i0..i0+127]
    __nv_bfloat16* ob = outp + ((size_t)bb*CH + hh*HD) * HW_;
    #pragma unroll
    for (int r = 0; r < 4; r++) {
        int idx = r*256 + tid;
        int d = idx >> 4, cc = (idx & 15) * 8;
        *(uint4*)&ob[(size_t)d*HW_ + i0 + cc] = *(const uint4*)&Qs[d*QSTR2 + cc];
    }
}

// ---------------------------------------------------------------------------
extern "C" void kernel_launch(void* const* d_in, const int* in_sizes, int n_in,
                              void* d_out, int out_size)
{
    const float* x      = (const float*)d_in[0];
    const float* gn_w   = (const float*)d_in[1];
    const float* gn_b   = (const float*)d_in[2];
    const float* qkv_w  = (const float*)d_in[3];
    const float* qkv_b  = (const float*)d_in[4];
    const float* proj_w = (const float*)d_in[5];
    const float* proj_b = (const float*)d_in[6];
    float* out = (float*)d_out;

    __nv_bfloat16 *xn, *qkvb, *att, *wq, *wp;
    cudaGetSymbolAddress((void**)&xn,   g_xn);
    cudaGetSymbolAddress((void**)&qkvb, g_qkv);
    cudaGetSymbolAddress((void**)&att,  g_att);
    cudaGetSymbolAddress((void**)&wq,   g_wq);
    cudaGetSymbolAddress((void**)&wp,   g_wp);

    cudaFuncSetAttribute(mma_gemm_kernel<true>,
                         cudaFuncAttributeMaxDynamicSharedMemorySize, GEMM_SMEM);
    cudaFuncSetAttribute(mma_gemm_kernel<false>,
                         cudaFuncAttributeMaxDynamicSharedMemorySize, GEMM_SMEM);
    cudaFuncSetAttribute(attention_kernel,
                         cudaFuncAttributeMaxDynamicSharedMemorySize, ATT_SMEM);

    // 0) weights fp32 -> bf16
    f2bf_kernel<<<(3*CH*CH/4 + 255)/256, 256>>>(qkv_w, wq, 3*CH*CH);
    f2bf_kernel<<<(CH*CH/4 + 255)/256, 256>>>(proj_w, wp, CH*CH);

    // 1) GroupNorm -> bf16
    groupnorm_kernel<<<BATCH*NGROUPS, 1024>>>(x, gn_w, gn_b, xn);

    // 2) qkv GEMM (bf16 out, q rows pre-scaled)
    mma_gemm_kernel<true><<<dim3(HW_/GBN, (3*CH)/GBM, BATCH), 256, GEMM_SMEM>>>(
        wq, xn, qkvb, qkv_b, (const float*)0, 3*CH, CH, HW_, CH);

    // 3) flash attention (128 queries/block, 8 warps)
    attention_kernel<<<dim3(HW_/128, BATCH*NH), 256, ATT_SMEM>>>(qkvb, att);

    // 4) proj GEMM (fp32 out + bias + residual)
    mma_gemm_kernel<false><<<dim3(HW_/GBN, CH/GBM, BATCH), 256, GEMM_SMEM>>>(
        wp, att, out, proj_b, x, CH, CH, HW_, 0);
}

// round 13
// speedup vs baseline: 1.0966x; 1.0966x over previous
#include <cuda_runtime.h>
#include <cuda_bf16.h>
#include <math.h>
#include <stdint.h>

#define BATCH   16
#define CH      512
#define HW_     1024
#define NGROUPS 8
#define CG      64
#define NH      8
#define HD      64
#define EPS_    1e-5f
#define QSC_    0.18033688f   // 0.125 * log2(e): softmax done in exp2 domain

// Scratch (allocation-free)
__device__ __nv_bfloat16 g_xn [BATCH*CH*HW_];
__device__ __nv_bfloat16 g_qkv[(size_t)BATCH*3*CH*HW_];
__device__ __nv_bfloat16 g_att[BATCH*CH*HW_];
__device__ __nv_bfloat16 g_wq [3*CH*CH];
__device__ __nv_bfloat16 g_wp [CH*CH];

// ---------------------------------------------------------------------------
// helpers
// ---------------------------------------------------------------------------
__device__ __forceinline__ uint32_t sptr(const void* p) {
    return (uint32_t)__cvta_generic_to_shared(p);
}
__device__ __forceinline__ uint32_t packbf(float a, float b) {
    __nv_bfloat162 t = __float22bfloat162_rn(make_float2(a, b));
    return *(uint32_t*)&t;
}
__device__ __forceinline__ void cpa16(uint32_t s, const void* g) {
    asm volatile("cp.async.cg.shared.global [%0],[%1],16;" :: "r"(s), "l"(g));
}
#define CP_COMMIT() asm volatile("cp.async.commit_group;")
#define CP_WAIT(n)  asm volatile("cp.async.wait_group %0;" :: "n"(n))

__device__ __forceinline__ void ldsm4(uint32_t* r, uint32_t a) {
    asm volatile("ldmatrix.sync.aligned.m8n8.x4.shared.b16 {%0,%1,%2,%3},[%4];"
        : "=r"(r[0]), "=r"(r[1]), "=r"(r[2]), "=r"(r[3]) : "r"(a));
}
__device__ __forceinline__ void ldsm4t(uint32_t* r, uint32_t a) {
    asm volatile("ldmatrix.sync.aligned.m8n8.x4.trans.shared.b16 {%0,%1,%2,%3},[%4];"
        : "=r"(r[0]), "=r"(r[1]), "=r"(r[2]), "=r"(r[3]) : "r"(a));
}
__device__ __forceinline__ void mma_bf16(float* c, const uint32_t* a, const uint32_t* b) {
    asm volatile("mma.sync.aligned.m16n8k16.row.col.f32.bf16.bf16.f32 "
        "{%0,%1,%2,%3},{%4,%5,%6,%7},{%8,%9},{%0,%1,%2,%3};"
        : "+f"(c[0]), "+f"(c[1]), "+f"(c[2]), "+f"(c[3])
        : "r"(a[0]), "r"(a[1]), "r"(a[2]), "r"(a[3]), "r"(b[0]), "r"(b[1]));
}

// ---------------------------------------------------------------------------
// fp32 -> bf16 weight conversion
// ---------------------------------------------------------------------------
__global__ void f2bf_kernel(const float* __restrict__ src,
                            __nv_bfloat16* __restrict__ dst, int n)
{
    int i = (blockIdx.x*blockDim.x + threadIdx.x) * 4;
    if (i < n) {
        float4 v = *(const float4*)&src[i];
        uint2 o;
        o.x = packbf(v.x, v.y);
        o.y = packbf(v.z, v.w);
        *(uint2*)&dst[i] = o;
    }
}

// ---------------------------------------------------------------------------
// GroupNorm -> bf16
// ---------------------------------------------------------------------------
__global__ void groupnorm_kernel(const float* __restrict__ x,
                                 const float* __restrict__ w,
                                 const float* __restrict__ bias,
                                 __nv_bfloat16* __restrict__ xn)
{
    int bg = blockIdx.x;
    int bb = bg / NGROUPS, g = bg % NGROUPS;
    const float*   xp = x  + ((size_t)bb*CH + g*CG) * HW_;
    __nv_bfloat16* op = xn + ((size_t)bb*CH + g*CG) * HW_;
    const int NEL = CG * HW_;
    int tid = threadIdx.x;

    float s = 0.f, ss = 0.f;
    for (int i = tid*4; i < NEL; i += blockDim.x*4) {
        float4 v = *(const float4*)&xp[i];
        s  += v.x + v.y + v.z + v.w;
        ss += v.x*v.x + v.y*v.y + v.z*v.z + v.w*v.w;
    }
    __shared__ float r1[1024], r2[1024];
    r1[tid] = s; r2[tid] = ss;
    __syncthreads();
    for (int st = 512; st > 0; st >>= 1) {
        if (tid < st) { r1[tid] += r1[tid+st]; r2[tid] += r2[tid+st]; }
        __syncthreads();
    }
    float mean = r1[0] * (1.f/NEL);
    float var  = r2[0] * (1.f/NEL) - mean*mean;
    float inv  = rsqrtf(var + EPS_);

    for (int i = tid*4; i < NEL; i += blockDim.x*4) {
        int ch = g*CG + (i >> 10);
        float wc = w[ch], bc = bias[ch];
        float4 v = *(const float4*)&xp[i];
        uint2 o;
        o.x = packbf((v.x - mean)*inv*wc + bc, (v.y - mean)*inv*wc + bc);
        o.y = packbf((v.z - mean)*inv*wc + bc, (v.w - mean)*inv*wc + bc);
        *(uint2*)&op[i] = o;
    }
}

// ---------------------------------------------------------------------------
// bf16 MMA GEMM: 128x256x32 tile, 8 warps (2x4), warp 64x64.
// 4-stage cp.async, single sync per K-iter, prefetch AFTER the MMA block.
// Crossbar model: 64KB LDSM + 24KB writes per kt for 512 HMMA -> ~65% ceiling.
// ---------------------------------------------------------------------------
#define GBM 128
#define GBN 256
#define GBK 32
#define ASTR 40
#define BSTR 264
#define A_ST (GBM*ASTR)                      // 5120 halves
#define B_ST (GBK*BSTR)                      // 8448 halves
#define GEMM_SMEM ((4*(A_ST + B_ST)) * 2)    // 108544 B

template<bool OUT_BF16>
__global__ __launch_bounds__(256, 1)
void mma_gemm_kernel(const __nv_bfloat16* __restrict__ A,
                     const __nv_bfloat16* __restrict__ Bbase,
                     void* __restrict__ Cbase,
                     const float* __restrict__ bias,
                     const float* __restrict__ Rbase,
                     int M, int K, int N, int q_rows)
{
    extern __shared__ __align__(16) uint16_t smg[];
    uint16_t* As = smg;              // [4][128*40]
    uint16_t* Bs = smg + 4*A_ST;     // [4][32*264]

    int bz = blockIdx.z;
    const __nv_bfloat16* Bm = Bbase + (size_t)bz * K * N;

    int m0 = blockIdx.y * GBM, n0 = blockIdx.x * GBN;
    int tid = threadIdx.x, lane = tid & 31, warp = tid >> 5;
    int wm = (warp >> 2) * 64, wn = (warp & 3) * 64;

    int arow = tid >> 1, acol = (tid & 1) * 16;
    int brow = tid >> 3, bcol = (tid & 7) * 8;

    const __nv_bfloat16* Ab = A + (size_t)(m0 + arow)*K + acol;
    const __nv_bfloat16* Bb = Bm + (size_t)brow*N + n0 + bcol;

    float c[4][8][4];
    #pragma unroll
    for (int mt = 0; mt < 4; mt++)
        #pragma unroll
        for (int nt = 0; nt < 8; nt++)
            #pragma unroll
            for (int e = 0; e < 4; e++) c[mt][nt][e] = 0.f;

    const int KT = K / GBK;

    // prologue: 3 stages in flight
    #pragma unroll
    for (int p = 0; p < 3; p++) {
        int st = p, k0 = p * GBK;
        cpa16(sptr(&As[st*A_ST + arow*ASTR + acol]),     Ab + k0);
        cpa16(sptr(&As[st*A_ST + arow*ASTR + acol + 8]), Ab + k0 + 8);
        #pragma unroll
        for (int j = 0; j < 4; j++)
            cpa16(sptr(&Bs[st*B_ST + brow*BSTR + bcol + j*64]),
                  Bb + (size_t)k0*N + j*64);
        CP_COMMIT();
    }

    for (int kt = 0; kt < KT; kt++) {
        CP_WAIT(2);
        __syncthreads();

        const uint16_t* Ac = As + (kt & 3)*A_ST;
        const uint16_t* Bc = Bs + (kt & 3)*B_ST;

        #pragma unroll
        for (int ks = 0; ks < 2; ks++) {
            uint32_t a[4][4], b[4][4];
            int g = lane >> 3;
            #pragma unroll
            for (int mt = 0; mt < 4; mt++) {
                int row = wm + mt*16 + (g & 1)*8 + (lane & 7);
                int col = ks*16 + (g >> 1)*8;
                ldsm4(a[mt], sptr(&Ac[row*ASTR + col]));
            }
            int kk = ks*16 + (lane & 15);
            int cb = (lane >> 4)*8;
            #pragma unroll
            for (int ntp = 0; ntp < 4; ntp++)
                ldsm4t(b[ntp], sptr(&Bc[kk*BSTR + wn + ntp*16 + cb]));
            #pragma unroll
            for (int mt = 0; mt < 4; mt++)
                #pragma unroll
                for (int ntp = 0; ntp < 4; ntp++) {
                    mma_bf16(c[mt][2*ntp],   a[mt], &b[ntp][0]);
                    mma_bf16(c[mt][2*ntp+1], a[mt], &b[ntp][2]);
                }
        }

        // prefetch stage kt+3 (buf (kt-1)%4: all reads done before sync above)
        if (kt + 3 < KT) {
            int st = (kt + 3) & 3, k0 = (kt + 3) * GBK;
            cpa16(sptr(&As[st*A_ST + arow*ASTR + acol]),     Ab + k0);
            cpa16(sptr(&As[st*A_ST + arow*ASTR + acol + 8]), Ab + k0 + 8);
            #pragma unroll
            for (int j = 0; j < 4; j++)
                cpa16(sptr(&Bs[st*B_ST + brow*BSTR + bcol + j*64]),
                      Bb + (size_t)k0*N + j*64);
        }
        CP_COMMIT();
    }

    // epilogue
    #pragma unroll
    for (int mt = 0; mt < 4; mt++) {
        #pragma unroll
        for (int half = 0; half < 2; half++) {
            int m = m0 + wm + mt*16 + (lane >> 2) + half*8;
            float bv = bias ? bias[m] : 0.f;
            #pragma unroll
            for (int nt = 0; nt < 8; nt++) {
                int n = n0 + wn + nt*8 + 2*(lane & 3);
                float x0 = c[mt][nt][half*2 + 0] + bv;
                float x1 = c[mt][nt][half*2 + 1] + bv;
                if (OUT_BF16) {
                    float sc = (m < q_rows) ? QSC_ : 1.0f;
                    *(uint32_t*)((__nv_bfloat16*)Cbase + (size_t)bz*M*N + (size_t)m*N + n)
                        = packbf(x0*sc, x1*sc);
                } else {
                    float2 o = make_float2(x0, x1);
                    if (Rbase) {
                        float2 r = *(const float2*)&Rbase[(size_t)bz*M*N + (size_t)m*N + n];
                        o.x += r.x; o.y += r.y;
                    }
                    *(float2*)((float*)Cbase + (size_t)bz*M*N + (size_t)m*N + n) = o;
                }
            }
        }
    }
}

// ---------------------------------------------------------------------------
// Flash attention (R10 config): 128 queries/block, 4 warps, 2 q-tiles share
// K/V frags, 3-stage cp.async, P in registers, softmax in exp2 domain
// (q pre-scaled by 0.125*log2e in the qkv epilogue).
// ---------------------------------------------------------------------------
#define KSTR 72
#define QSTR2 136
#define OFF_KS (64*QSTR2)
#define OFF_VS (OFF_KS + 3*64*KSTR)
#define ATT_SMEM_HALVES (OFF_VS + 3*64*KSTR)
#define ATT_SMEM (ATT_SMEM_HALVES * 2)         // 72704 B

__global__ __launch_bounds__(128)
void attention_kernel(const __nv_bfloat16* __restrict__ qkv,
                      __nv_bfloat16* __restrict__ outp)
{
    extern __shared__ __align__(16) uint16_t sm[];
    uint16_t* Qs = sm;            // [64][136] — Q stage, then O stage
    uint16_t* Ks = sm + OFF_KS;   // [3][64][72]
    uint16_t* Vs = sm + OFF_VS;   // [3][64][72]

    int bh = blockIdx.y;
    int bb = bh >> 3, hh = bh & 7;
    int i0 = blockIdx.x * 128;
    const __nv_bfloat16* qp = qkv + ((size_t)bb*3*CH + hh*HD) * HW_;
    const __nv_bfloat16* kp = qp + (size_t)CH * HW_;
    const __nv_bfloat16* vp = qp + (size_t)2*CH * HW_;

    int tid = threadIdx.x, lane = tid & 31, warp = tid >> 5;

    // prologue: group0 = Q + KV tile 0; group1 = KV tile 1
    #pragma unroll
    for (int r = 0; r < 8; r++) {
        int idx = r*128 + tid;
        int d = idx >> 4, cc = (idx & 15) * 8;
        cpa16(sptr(&Qs[d*QSTR2 + cc]), qp + (size_t)d*HW_ + i0 + cc);
    }
    #pragma unroll
    for (int r = 0; r < 4; r++) {
        int idx = r*128 + tid;
        int d = idx >> 3, cc = (idx & 7) * 8;
        cpa16(sptr(&Ks[d*KSTR + cc]), kp + (size_t)d*HW_ + cc);
        cpa16(sptr(&Vs[d*KSTR + cc]), vp + (size_t)d*HW_ + cc);
    }
    CP_COMMIT();
    #pragma unroll
    for (int r = 0; r < 4; r++) {
        int idx = r*128 + tid;
        int d = idx >> 3, cc = (idx & 7) * 8;
        cpa16(sptr(&Ks[64*KSTR + d*KSTR + cc]), kp + (size_t)d*HW_ + 64 + cc);
        cpa16(sptr(&Vs[64*KSTR + d*KSTR + cc]), vp + (size_t)d*HW_ + 64 + cc);
    }
    CP_COMMIT();

    uint32_t qf[2][4][4];
    float mx[2][2], l[2][2];
    float o[2][8][4];
    #pragma unroll
    for (int t = 0; t < 2; t++) {
        mx[t][0] = mx[t][1] = -1e30f;
        l[t][0] = l[t][1] = 0.f;
        #pragma unroll
        for (int nt = 0; nt < 8; nt++)
            #pragma unroll
            for (int e = 0; e < 4; e++) o[t][nt][e] = 0.f;
    }

    for (int jt = 0; jt < 16; jt++) {
        CP_WAIT(1);
        __syncthreads();

        if (jt == 0) {   // Q frags (register-resident afterwards)
            int g = lane >> 3;
            int kq = (g >> 1)*8 + (lane & 7);
            #pragma unroll
            for (int t = 0; t < 2; t++) {
                int mq = t*64 + warp*16 + (g & 1)*8;
                #pragma unroll
                for (int ks = 0; ks < 4; ks++)
                    ldsm4t(qf[t][ks], sptr(&Qs[(ks*16 + kq)*QSTR2 + mq]));
            }
        }

        const uint16_t* Kc = Ks + (jt % 3)*64*KSTR;
        const uint16_t* Vc = Vs + (jt % 3)*64*KSTR;

        // S = Q K^T (both q-tiles share K frags)
        float s[2][8][4];
        #pragma unroll
        for (int t = 0; t < 2; t++)
            #pragma unroll
            for (int nt = 0; nt < 8; nt++)
                #pragma unroll
                for (int e = 0; e < 4; e++) s[t][nt][e] = 0.f;

        #pragma unroll
        for (int ks = 0; ks < 4; ks++) {
            int kk = ks*16 + (lane & 15);
            int cb = (lane >> 4)*8;
            #pragma unroll
            for (int ntp = 0; ntp < 4; ntp++) {
                uint32_t b[4];
                ldsm4t(b, sptr(&Kc[kk*KSTR + ntp*16 + cb]));
                #pragma unroll
                for (int t = 0; t < 2; t++) {
                    mma_bf16(s[t][2*ntp],   qf[t][ks], &b[0]);
                    mma_bf16(s[t][2*ntp+1], qf[t][ks], &b[2]);
                }
            }
        }

        // online softmax per q-tile — exp2 domain
        #pragma unroll
        for (int t = 0; t < 2; t++) {
            float rmax0 = -1e30f, rmax1 = -1e30f;
            #pragma unroll
            for (int nt = 0; nt < 8; nt++) {
                rmax0 = fmaxf(rmax0, fmaxf(s[t][nt][0], s[t][nt][1]));
                rmax1 = fmaxf(rmax1, fmaxf(s[t][nt][2], s[t][nt][3]));
            }
            #pragma unroll
            for (int off = 1; off < 4; off <<= 1) {
                rmax0 = fmaxf(rmax0, __shfl_xor_sync(0xffffffffu, rmax0, off));
                rmax1 = fmaxf(rmax1, __shfl_xor_sync(0xffffffffu, rmax1, off));
            }
            float mn0 = fmaxf(mx[t][0], rmax0), mn1 = fmaxf(mx[t][1], rmax1);
            float corr0 = exp2f(mx[t][0] - mn0), corr1 = exp2f(mx[t][1] - mn1);
            mx[t][0] = mn0; mx[t][1] = mn1;

            float rs0 = 0.f, rs1 = 0.f;
            #pragma unroll
            for (int nt = 0; nt < 8; nt++) {
                s[t][nt][0] = exp2f(s[t][nt][0] - mn0);
                s[t][nt][1] = exp2f(s[t][nt][1] - mn0);
                s[t][nt][2] = exp2f(s[t][nt][2] - mn1);
                s[t][nt][3] = exp2f(s[t][nt][3] - mn1);
                rs0 += s[t][nt][0] + s[t][nt][1];
                rs1 += s[t][nt][2] + s[t][nt][3];
            }
            #pragma unroll
            for (int off = 1; off < 4; off <<= 1) {
                rs0 += __shfl_xor_sync(0xffffffffu, rs0, off);
                rs1 += __shfl_xor_sync(0xffffffffu, rs1, off);
            }
            l[t][0] = l[t][0]*corr0 + rs0;
            l[t][1] = l[t][1]*corr1 + rs1;
            #pragma unroll
            for (int nt = 0; nt < 8; nt++) {
                o[t][nt][0] *= corr0; o[t][nt][1] *= corr0;
                o[t][nt][2] *= corr1; o[t][nt][3] *= corr1;
            }
        }

        // O += P @ V — P A-frags straight from S C-frags (no smem round-trip)
        #pragma unroll
        for (int ks = 0; ks < 4; ks++) {
            uint32_t pa[2][4];
            #pragma unroll
            for (int t = 0; t < 2; t++) {
                pa[t][0] = packbf(s[t][2*ks][0],   s[t][2*ks][1]);
                pa[t][1] = packbf(s[t][2*ks][2],   s[t][2*ks][3]);
                pa[t][2] = packbf(s[t][2*ks+1][0], s[t][2*ks+1][1]);
                pa[t][3] = packbf(s[t][2*ks+1][2], s[t][2*ks+1][3]);
            }
            int jc = ks*16 + ((lane >> 3) & 1)*8;
            int dbase = (lane >> 4)*8 + (lane & 7);
            #pragma unroll
            for (int ntp = 0; ntp < 4; ntp++) {
                uint32_t b[4];
                ldsm4(b, sptr(&Vc[(ntp*16 + dbase)*KSTR + jc]));
                #pragma unroll
                for (int t = 0; t < 2; t++) {
                    mma_bf16(o[t][2*ntp],   pa[t], &b[0]);
                    mma_bf16(o[t][2*ntp+1], pa[t], &b[2]);
                }
            }
        }

        // issue KV tile jt+2 (stage (jt-1)%3: readers done before sync above)
        if (jt + 2 < 16) {
            int stp = (jt + 2) % 3;
            int j0 = (jt + 2) * 64;
            #pragma unroll
            for (int r = 0; r < 4; r++) {
                int idx = r*128 + tid;
                int d = idx >> 3, cc = (idx & 7) * 8;
                cpa16(sptr(&Ks[stp*64*KSTR + d*KSTR + cc]), kp + (size_t)d*HW_ + j0 + cc);
                cpa16(sptr(&Vs[stp*64*KSTR + d*KSTR + cc]), vp + (size_t)d*HW_ + j0 + cc);
            }
        }
        CP_COMMIT();
    }

    // normalize + stage O as bf16 [d][i] into Qs (Q long consumed)
    __syncthreads();
    {
        __nv_bfloat16* Od = (__nv_bfloat16*)Qs;
        #pragma unroll
        for (int t = 0; t < 2; t++) {
            float inv0 = 1.f / l[t][0], inv1 = 1.f / l[t][1];
            int iq = t*64 + warp*16 + (lane >> 2);
            #pragma unroll
            for (int nt = 0; nt < 8; nt++) {
                int d = nt*8 + 2*(lane & 3);
                Od[(size_t)d*QSTR2 + iq]         = __float2bfloat16_rn(o[t][nt][0]*inv0);
                Od[(size_t)(d+1)*QSTR2 + iq]     = __float2bfloat16_rn(o[t][nt][1]*inv0);
                Od[(size_t)d*QSTR2 + iq + 8]     = __float2bfloat16_rn(o[t][nt][2]*inv1);
                Od[(size_t)(d+1)*QSTR2 + iq + 8] = __float2bfloat16_rn(o[t][nt][3]*inv1);
            }
        }
    }
    __syncthreads();

    // coalesced store out[d][i0..i0+127]
    __nv_bfloat16* ob = outp + ((size_t)bb*CH + hh*HD) * HW_;
    #pragma unroll
    for (int r = 0; r < 8; r++) {
        int idx = r*128 + tid;
        int d = idx >> 4, cc = (idx & 15) * 8;
        *(uint4*)&ob[(size_t)d*HW_ + i0 + cc] = *(const uint4*)&Qs[d*QSTR2 + cc];
    }
}

// ---------------------------------------------------------------------------
extern "C" void kernel_launch(void* const* d_in, const int* in_sizes, int n_in,
                              void* d_out, int out_size)
{
    const float* x      = (const float*)d_in[0];
    const float* gn_w   = (const float*)d_in[1];
    const float* gn_b   = (const float*)d_in[2];
    const float* qkv_w  = (const float*)d_in[3];
    const float* qkv_b  = (const float*)d_in[4];
    const float* proj_w = (const float*)d_in[5];
    const float* proj_b = (const float*)d_in[6];
    float* out = (float*)d_out;

    __nv_bfloat16 *xn, *qkvb, *att, *wq, *wp;
    cudaGetSymbolAddress((void**)&xn,   g_xn);
    cudaGetSymbolAddress((void**)&qkvb, g_qkv);
    cudaGetSymbolAddress((void**)&att,  g_att);
    cudaGetSymbolAddress((void**)&wq,   g_wq);
    cudaGetSymbolAddress((void**)&wp,   g_wp);

    cudaFuncSetAttribute(mma_gemm_kernel<true>,
                         cudaFuncAttributeMaxDynamicSharedMemorySize, GEMM_SMEM);
    cudaFuncSetAttribute(mma_gemm_kernel<false>,
                         cudaFuncAttributeMaxDynamicSharedMemorySize, GEMM_SMEM);
    cudaFuncSetAttribute(attention_kernel,
                         cudaFuncAttributeMaxDynamicSharedMemorySize, ATT_SMEM);

    // 0) weights fp32 -> bf16
    f2bf_kernel<<<(3*CH*CH/4 + 255)/256, 256>>>(qkv_w, wq, 3*CH*CH);
    f2bf_kernel<<<(CH*CH/4 + 255)/256, 256>>>(proj_w, wp, CH*CH);

    // 1) GroupNorm -> bf16
    groupnorm_kernel<<<BATCH*NGROUPS, 1024>>>(x, gn_w, gn_b, xn);

    // 2) qkv GEMM (bf16 out, q rows pre-scaled by 0.125*log2e)
    mma_gemm_kernel<true><<<dim3(HW_/GBN, (3*CH)/GBM, BATCH), 256, GEMM_SMEM>>>(
        wq, xn, qkvb, qkv_b, (const float*)0, 3*CH, CH, HW_, CH);

    // 3) flash attention (128 queries/block, 4 warps, exp2 softmax)
    attention_kernel<<<dim3(HW_/128, BATCH*NH), 128, ATT_SMEM>>>(qkvb, att);

    // 4) proj GEMM (fp32 out + bias + residual)
    mma_gemm_kernel<false><<<dim3(HW_/GBN, CH/GBM, BATCH), 256, GEMM_SMEM>>>(
        wp, att, out, proj_b, x, CH, CH, HW_, 0);
}

// round 14
// speedup vs baseline: 1.1392x; 1.0389x over previous
#include <cuda_runtime.h>
#include <cuda_bf16.h>
#include <math.h>
#include <stdint.h>

#define BATCH   16
#define CH      512
#define HW_     1024
#define NGROUPS 8
#define CG      64
#define NH      8
#define HD      64
#define EPS_    1e-5f
#define QSC_    0.18033688f   // 0.125 * log2(e): softmax done in exp2 domain

// Scratch (allocation-free)
__device__ __nv_bfloat16 g_xn [BATCH*CH*HW_];
__device__ __nv_bfloat16 g_qkv[(size_t)BATCH*3*CH*HW_];
__device__ __nv_bfloat16 g_att[BATCH*CH*HW_];
__device__ __nv_bfloat16 g_wq [3*CH*CH];
__device__ __nv_bfloat16 g_wp [CH*CH];

// ---------------------------------------------------------------------------
// helpers
// ---------------------------------------------------------------------------
__device__ __forceinline__ uint32_t sptr(const void* p) {
    return (uint32_t)__cvta_generic_to_shared(p);
}
__device__ __forceinline__ uint32_t packbf(float a, float b) {
    __nv_bfloat162 t = __float22bfloat162_rn(make_float2(a, b));
    return *(uint32_t*)&t;
}
__device__ __forceinline__ void cpa16(uint32_t s, const void* g) {
    asm volatile("cp.async.cg.shared.global [%0],[%1],16;" :: "r"(s), "l"(g));
}
#define CP_COMMIT() asm volatile("cp.async.commit_group;")
#define CP_WAIT(n)  asm volatile("cp.async.wait_group %0;" :: "n"(n))

__device__ __forceinline__ void ldsm4(uint32_t* r, uint32_t a) {
    asm volatile("ldmatrix.sync.aligned.m8n8.x4.shared.b16 {%0,%1,%2,%3},[%4];"
        : "=r"(r[0]), "=r"(r[1]), "=r"(r[2]), "=r"(r[3]) : "r"(a));
}
__device__ __forceinline__ void ldsm4t(uint32_t* r, uint32_t a) {
    asm volatile("ldmatrix.sync.aligned.m8n8.x4.trans.shared.b16 {%0,%1,%2,%3},[%4];"
        : "=r"(r[0]), "=r"(r[1]), "=r"(r[2]), "=r"(r[3]) : "r"(a));
}
__device__ __forceinline__ void mma_bf16(float* c, const uint32_t* a, const uint32_t* b) {
    asm volatile("mma.sync.aligned.m16n8k16.row.col.f32.bf16.bf16.f32 "
        "{%0,%1,%2,%3},{%4,%5,%6,%7},{%8,%9},{%0,%1,%2,%3};"
        : "+f"(c[0]), "+f"(c[1]), "+f"(c[2]), "+f"(c[3])
        : "r"(a[0]), "r"(a[1]), "r"(a[2]), "r"(a[3]), "r"(b[0]), "r"(b[1]));
}

// ---------------------------------------------------------------------------
// fp32 -> bf16 weight conversion
// ---------------------------------------------------------------------------
__global__ void f2bf_kernel(const float* __restrict__ src,
                            __nv_bfloat16* __restrict__ dst, int n)
{
    int i = (blockIdx.x*blockDim.x + threadIdx.x) * 4;
    if (i < n) {
        float4 v = *(const float4*)&src[i];
        uint2 o;
        o.x = packbf(v.x, v.y);
        o.y = packbf(v.z, v.w);
        *(uint2*)&dst[i] = o;
    }
}

// ---------------------------------------------------------------------------
// GroupNorm -> bf16
// ---------------------------------------------------------------------------
__global__ void groupnorm_kernel(const float* __restrict__ x,
                                 const float* __restrict__ w,
                                 const float* __restrict__ bias,
                                 __nv_bfloat16* __restrict__ xn)
{
    int bg = blockIdx.x;
    int bb = bg / NGROUPS, g = bg % NGROUPS;
    const float*   xp = x  + ((size_t)bb*CH + g*CG) * HW_;
    __nv_bfloat16* op = xn + ((size_t)bb*CH + g*CG) * HW_;
    const int NEL = CG * HW_;
    int tid = threadIdx.x;

    float s = 0.f, ss = 0.f;
    for (int i = tid*4; i < NEL; i += blockDim.x*4) {
        float4 v = *(const float4*)&xp[i];
        s  += v.x + v.y + v.z + v.w;
        ss += v.x*v.x + v.y*v.y + v.z*v.z + v.w*v.w;
    }
    __shared__ float r1[1024], r2[1024];
    r1[tid] = s; r2[tid] = ss;
    __syncthreads();
    for (int st = 512; st > 0; st >>= 1) {
        if (tid < st) { r1[tid] += r1[tid+st]; r2[tid] += r2[tid+st]; }
        __syncthreads();
    }
    float mean = r1[0] * (1.f/NEL);
    float var  = r2[0] * (1.f/NEL) - mean*mean;
    float inv  = rsqrtf(var + EPS_);

    for (int i = tid*4; i < NEL; i += blockDim.x*4) {
        int ch = g*CG + (i >> 10);
        float wc = w[ch], bc = bias[ch];
        float4 v = *(const float4*)&xp[i];
        uint2 o;
        o.x = packbf((v.x - mean)*inv*wc + bc, (v.y - mean)*inv*wc + bc);
        o.y = packbf((v.z - mean)*inv*wc + bc, (v.w - mean)*inv*wc + bc);
        *(uint2*)&op[i] = o;
    }
}

// ---------------------------------------------------------------------------
// bf16 MMA GEMM: 128x256x32 tile, 512 threads = 16 warps (4x4), warp 32x64.
// Same smem traffic as R13 per kt, but 4 warps/SMSP for latency hiding.
// ---------------------------------------------------------------------------
#define GBM 128
#define GBN 256
#define GBK 32
#define ASTR 40
#define BSTR 264
#define A_ST (GBM*ASTR)                      // 5120 halves
#define B_ST (GBK*BSTR)                      // 8448 halves
#define GEMM_SMEM ((4*(A_ST + B_ST)) * 2)    // 108544 B

template<bool OUT_BF16>
__global__ __launch_bounds__(512, 1)
void mma_gemm_kernel(const __nv_bfloat16* __restrict__ A,
                     const __nv_bfloat16* __restrict__ Bbase,
                     void* __restrict__ Cbase,
                     const float* __restrict__ bias,
                     const float* __restrict__ Rbase,
                     int M, int K, int N, int q_rows)
{
    extern __shared__ __align__(16) uint16_t smg[];
    uint16_t* As = smg;              // [4][128*40]
    uint16_t* Bs = smg + 4*A_ST;     // [4][32*264]

    int bz = blockIdx.z;
    const __nv_bfloat16* Bm = Bbase + (size_t)bz * K * N;

    int m0 = blockIdx.y * GBM, n0 = blockIdx.x * GBN;
    int tid = threadIdx.x, lane = tid & 31, warp = tid >> 5;
    int wm = (warp >> 2) * 32, wn = (warp & 3) * 64;

    // loaders: A 128x32 halves -> 512 cpa16 (1/thread); B 32x256 -> 1024 (2/thread)
    int arow = tid >> 2,  acol = (tid & 3) * 8;
    int brow = tid >> 5,  bcol = (tid & 31) * 8;

    const __nv_bfloat16* Ab = A + (size_t)(m0 + arow)*K + acol;
    const __nv_bfloat16* Bb0 = Bm + (size_t)brow*N      + n0 + bcol;
    const __nv_bfloat16* Bb1 = Bm + (size_t)(brow+16)*N + n0 + bcol;

    float c[2][8][4];
    #pragma unroll
    for (int mt = 0; mt < 2; mt++)
        #pragma unroll
        for (int nt = 0; nt < 8; nt++)
            #pragma unroll
            for (int e = 0; e < 4; e++) c[mt][nt][e] = 0.f;

    const int KT = K / GBK;

    // prologue: 3 stages in flight
    #pragma unroll
    for (int p = 0; p < 3; p++) {
        int st = p, k0 = p * GBK;
        cpa16(sptr(&As[st*A_ST + arow*ASTR + acol]), Ab + k0);
        cpa16(sptr(&Bs[st*B_ST + brow*BSTR + bcol]),      Bb0 + (size_t)k0*N);
        cpa16(sptr(&Bs[st*B_ST + (brow+16)*BSTR + bcol]), Bb1 + (size_t)k0*N);
        CP_COMMIT();
    }

    for (int kt = 0; kt < KT; kt++) {
        CP_WAIT(2);
        __syncthreads();

        const uint16_t* Ac = As + (kt & 3)*A_ST;
        const uint16_t* Bc = Bs + (kt & 3)*B_ST;

        #pragma unroll
        for (int ks = 0; ks < 2; ks++) {
            uint32_t a[2][4], b[4][4];
            int g = lane >> 3;
            #pragma unroll
            for (int mt = 0; mt < 2; mt++) {
                int row = wm + mt*16 + (g & 1)*8 + (lane & 7);
                int col = ks*16 + (g >> 1)*8;
                ldsm4(a[mt], sptr(&Ac[row*ASTR + col]));
            }
            int kk = ks*16 + (lane & 15);
            int cb = (lane >> 4)*8;
            #pragma unroll
            for (int ntp = 0; ntp < 4; ntp++)
                ldsm4t(b[ntp], sptr(&Bc[kk*BSTR + wn + ntp*16 + cb]));
            #pragma unroll
            for (int mt = 0; mt < 2; mt++)
                #pragma unroll
                for (int ntp = 0; ntp < 4; ntp++) {
                    mma_bf16(c[mt][2*ntp],   a[mt], &b[ntp][0]);
                    mma_bf16(c[mt][2*ntp+1], a[mt], &b[ntp][2]);
                }
        }

        // prefetch stage kt+3 (buf (kt-1)%4: all reads done before sync above)
        if (kt + 3 < KT) {
            int st = (kt + 3) & 3, k0 = (kt + 3) * GBK;
            cpa16(sptr(&As[st*A_ST + arow*ASTR + acol]), Ab + k0);
            cpa16(sptr(&Bs[st*B_ST + brow*BSTR + bcol]),      Bb0 + (size_t)k0*N);
            cpa16(sptr(&Bs[st*B_ST + (brow+16)*BSTR + bcol]), Bb1 + (size_t)k0*N);
        }
        CP_COMMIT();
    }

    // epilogue
    #pragma unroll
    for (int mt = 0; mt < 2; mt++) {
        #pragma unroll
        for (int half = 0; half < 2; half++) {
            int m = m0 + wm + mt*16 + (lane >> 2) + half*8;
            float bv = bias ? bias[m] : 0.f;
            #pragma unroll
            for (int nt = 0; nt < 8; nt++) {
                int n = n0 + wn + nt*8 + 2*(lane & 3);
                float x0 = c[mt][nt][half*2 + 0] + bv;
                float x1 = c[mt][nt][half*2 + 1] + bv;
                if (OUT_BF16) {
                    float sc = (m < q_rows) ? QSC_ : 1.0f;
                    *(uint32_t*)((__nv_bfloat16*)Cbase + (size_t)bz*M*N + (size_t)m*N + n)
                        = packbf(x0*sc, x1*sc);
                } else {
                    float2 o = make_float2(x0, x1);
                    if (Rbase) {
                        float2 r = *(const float2*)&Rbase[(size_t)bz*M*N + (size_t)m*N + n];
                        o.x += r.x; o.y += r.y;
                    }
                    *(float2*)((float*)Cbase + (size_t)bz*M*N + (size_t)m*N + n) = o;
                }
            }
        }
    }
}

// ---------------------------------------------------------------------------
// Flash attention (R13): 128 queries/block, 4 warps, 2 q-tiles share K/V
// frags, 3-stage cp.async, P in registers, softmax in exp2 domain.
// ---------------------------------------------------------------------------
#define KSTR 72
#define QSTR2 136
#define OFF_KS (64*QSTR2)
#define OFF_VS (OFF_KS + 3*64*KSTR)
#define ATT_SMEM_HALVES (OFF_VS + 3*64*KSTR)
#define ATT_SMEM (ATT_SMEM_HALVES * 2)         // 72704 B

__global__ __launch_bounds__(128)
void attention_kernel(const __nv_bfloat16* __restrict__ qkv,
                      __nv_bfloat16* __restrict__ outp)
{
    extern __shared__ __align__(16) uint16_t sm[];
    uint16_t* Qs = sm;            // [64][136] — Q stage, then O stage
    uint16_t* Ks = sm + OFF_KS;   // [3][64][72]
    uint16_t* Vs = sm + OFF_VS;   // [3][64][72]

    int bh = blockIdx.y;
    int bb = bh >> 3, hh = bh & 7;
    int i0 = blockIdx.x * 128;
    const __nv_bfloat16* qp = qkv + ((size_t)bb*3*CH + hh*HD) * HW_;
    const __nv_bfloat16* kp = qp + (size_t)CH * HW_;
    const __nv_bfloat16* vp = qp + (size_t)2*CH * HW_;

    int tid = threadIdx.x, lane = tid & 31, warp = tid >> 5;

    #pragma unroll
    for (int r = 0; r < 8; r++) {
        int idx = r*128 + tid;
        int d = idx >> 4, cc = (idx & 15) * 8;
        cpa16(sptr(&Qs[d*QSTR2 + cc]), qp + (size_t)d*HW_ + i0 + cc);
    }
    #pragma unroll
    for (int r = 0; r < 4; r++) {
        int idx = r*128 + tid;
        int d = idx >> 3, cc = (idx & 7) * 8;
        cpa16(sptr(&Ks[d*KSTR + cc]), kp + (size_t)d*HW_ + cc);
        cpa16(sptr(&Vs[d*KSTR + cc]), vp + (size_t)d*HW_ + cc);
    }
    CP_COMMIT();
    #pragma unroll
    for (int r = 0; r < 4; r++) {
        int idx = r*128 + tid;
        int d = idx >> 3, cc = (idx & 7) * 8;
        cpa16(sptr(&Ks[64*KSTR + d*KSTR + cc]), kp + (size_t)d*HW_ + 64 + cc);
        cpa16(sptr(&Vs[64*KSTR + d*KSTR + cc]), vp + (size_t)d*HW_ + 64 + cc);
    }
    CP_COMMIT();

    uint32_t qf[2][4][4];
    float mx[2][2], l[2][2];
    float o[2][8][4];
    #pragma unroll
    for (int t = 0; t < 2; t++) {
        mx[t][0] = mx[t][1] = -1e30f;
        l[t][0] = l[t][1] = 0.f;
        #pragma unroll
        for (int nt = 0; nt < 8; nt++)
            #pragma unroll
            for (int e = 0; e < 4; e++) o[t][nt][e] = 0.f;
    }

    for (int jt = 0; jt < 16; jt++) {
        CP_WAIT(1);
        __syncthreads();

        if (jt == 0) {
            int g = lane >> 3;
            int kq = (g >> 1)*8 + (lane & 7);
            #pragma unroll
            for (int t = 0; t < 2; t++) {
                int mq = t*64 + warp*16 + (g & 1)*8;
                #pragma unroll
                for (int ks = 0; ks < 4; ks++)
                    ldsm4t(qf[t][ks], sptr(&Qs[(ks*16 + kq)*QSTR2 + mq]));
            }
        }

        const uint16_t* Kc = Ks + (jt % 3)*64*KSTR;
        const uint16_t* Vc = Vs + (jt % 3)*64*KSTR;

        float s[2][8][4];
        #pragma unroll
        for (int t = 0; t < 2; t++)
            #pragma unroll
            for (int nt = 0; nt < 8; nt++)
                #pragma unroll
                for (int e = 0; e < 4; e++) s[t][nt][e] = 0.f;

        #pragma unroll
        for (int ks = 0; ks < 4; ks++) {
            int kk = ks*16 + (lane & 15);
            int cb = (lane >> 4)*8;
            #pragma unroll
            for (int ntp = 0; ntp < 4; ntp++) {
                uint32_t b[4];
                ldsm4t(b, sptr(&Kc[kk*KSTR + ntp*16 + cb]));
                #pragma unroll
                for (int t = 0; t < 2; t++) {
                    mma_bf16(s[t][2*ntp],   qf[t][ks], &b[0]);
                    mma_bf16(s[t][2*ntp+1], qf[t][ks], &b[2]);
                }
            }
        }

        #pragma unroll
        for (int t = 0; t < 2; t++) {
            float rmax0 = -1e30f, rmax1 = -1e30f;
            #pragma unroll
            for (int nt = 0; nt < 8; nt++) {
                rmax0 = fmaxf(rmax0, fmaxf(s[t][nt][0], s[t][nt][1]));
                rmax1 = fmaxf(rmax1, fmaxf(s[t][nt][2], s[t][nt][3]));
            }
            #pragma unroll
            for (int off = 1; off < 4; off <<= 1) {
                rmax0 = fmaxf(rmax0, __shfl_xor_sync(0xffffffffu, rmax0, off));
                rmax1 = fmaxf(rmax1, __shfl_xor_sync(0xffffffffu, rmax1, off));
            }
            float mn0 = fmaxf(mx[t][0], rmax0), mn1 = fmaxf(mx[t][1], rmax1);
            float corr0 = exp2f(mx[t][0] - mn0), corr1 = exp2f(mx[t][1] - mn1);
            mx[t][0] = mn0; mx[t][1] = mn1;

            float rs0 = 0.f, rs1 = 0.f;
            #pragma unroll
            for (int nt = 0; nt < 8; nt++) {
                s[t][nt][0] = exp2f(s[t][nt][0] - mn0);
                s[t][nt][1] = exp2f(s[t][nt][1] - mn0);
                s[t][nt][2] = exp2f(s[t][nt][2] - mn1);
                s[t][nt][3] = exp2f(s[t][nt][3] - mn1);
                rs0 += s[t][nt][0] + s[t][nt][1];
                rs1 += s[t][nt][2] + s[t][nt][3];
            }
            #pragma unroll
            for (int off = 1; off < 4; off <<= 1) {
                rs0 += __shfl_xor_sync(0xffffffffu, rs0, off);
                rs1 += __shfl_xor_sync(0xffffffffu, rs1, off);
            }
            l[t][0] = l[t][0]*corr0 + rs0;
            l[t][1] = l[t][1]*corr1 + rs1;
            #pragma unroll
            for (int nt = 0; nt < 8; nt++) {
                o[t][nt][0] *= corr0; o[t][nt][1] *= corr0;
                o[t][nt][2] *= corr1; o[t][nt][3] *= corr1;
            }
        }

        #pragma unroll
        for (int ks = 0; ks < 4; ks++) {
            uint32_t pa[2][4];
            #pragma unroll
            for (int t = 0; t < 2; t++) {
                pa[t][0] = packbf(s[t][2*ks][0],   s[t][2*ks][1]);
                pa[t][1] = packbf(s[t][2*ks][2],   s[t][2*ks][3]);
                pa[t][2] = packbf(s[t][2*ks+1][0], s[t][2*ks+1][1]);
                pa[t][3] = packbf(s[t][2*ks+1][2], s[t][2*ks+1][3]);
            }
            int jc = ks*16 + ((lane >> 3) & 1)*8;
            int dbase = (lane >> 4)*8 + (lane & 7);
            #pragma unroll
            for (int ntp = 0; ntp < 4; ntp++) {
                uint32_t b[4];
                ldsm4(b, sptr(&Vc[(ntp*16 + dbase)*KSTR + jc]));
                #pragma unroll
                for (int t = 0; t < 2; t++) {
                    mma_bf16(o[t][2*ntp],   pa[t], &b[0]);
                    mma_bf16(o[t][2*ntp+1], pa[t], &b[2]);
                }
            }
        }

        if (jt + 2 < 16) {
            int stp = (jt + 2) % 3;
            int j0 = (jt + 2) * 64;
            #pragma unroll
            for (int r = 0; r < 4; r++) {
                int idx = r*128 + tid;
                int d = idx >> 3, cc = (idx & 7) * 8;
                cpa16(sptr(&Ks[stp*64*KSTR + d*KSTR + cc]), kp + (size_t)d*HW_ + j0 + cc);
                cpa16(sptr(&Vs[stp*64*KSTR + d*KSTR + cc]), vp + (size_t)d*HW_ + j0 + cc);
            }
        }
        CP_COMMIT();
    }

    __syncthreads();
    {
        __nv_bfloat16* Od = (__nv_bfloat16*)Qs;
        #pragma unroll
        for (int t = 0; t < 2; t++) {
            float inv0 = 1.f / l[t][0], inv1 = 1.f / l[t][1];
            int iq = t*64 + warp*16 + (lane >> 2);
            #pragma unroll
            for (int nt = 0; nt < 8; nt++) {
                int d = nt*8 + 2*(lane & 3);
                Od[(size_t)d*QSTR2 + iq]         = __float2bfloat16_rn(o[t][nt][0]*inv0);
                Od[(size_t)(d+1)*QSTR2 + iq]     = __float2bfloat16_rn(o[t][nt][1]*inv0);
                Od[(size_t)d*QSTR2 + iq + 8]     = __float2bfloat16_rn(o[t][nt][2]*inv1);
                Od[(size_t)(d+1)*QSTR2 + iq + 8] = __float2bfloat16_rn(o[t][nt][3]*inv1);
            }
        }
    }
    __syncthreads();

    __nv_bfloat16* ob = outp + ((size_t)bb*CH + hh*HD) * HW_;
    #pragma unroll
    for (int r = 0; r < 8; r++) {
        int idx = r*128 + tid;
        int d = idx >> 4, cc = (idx & 15) * 8;
        *(uint4*)&ob[(size_t)d*HW_ + i0 + cc] = *(const uint4*)&Qs[d*QSTR2 + cc];
    }
}

// ---------------------------------------------------------------------------
extern "C" void kernel_launch(void* const* d_in, const int* in_sizes, int n_in,
                              void* d_out, int out_size)
{
    const float* x      = (const float*)d_in[0];
    const float* gn_w   = (const float*)d_in[1];
    const float* gn_b   = (const float*)d_in[2];
    const float* qkv_w  = (const float*)d_in[3];
    const float* qkv_b  = (const float*)d_in[4];
    const float* proj_w = (const float*)d_in[5];
    const float* proj_b = (const float*)d_in[6];
    float* out = (float*)d_out;

    __nv_bfloat16 *xn, *qkvb, *att, *wq, *wp;
    cudaGetSymbolAddress((void**)&xn,   g_xn);
    cudaGetSymbolAddress((void**)&qkvb, g_qkv);
    cudaGetSymbolAddress((void**)&att,  g_att);
    cudaGetSymbolAddress((void**)&wq,   g_wq);
    cudaGetSymbolAddress((void**)&wp,   g_wp);

    cudaFuncSetAttribute(mma_gemm_kernel<true>,
                         cudaFuncAttributeMaxDynamicSharedMemorySize, GEMM_SMEM);
    cudaFuncSetAttribute(mma_gemm_kernel<false>,
                         cudaFuncAttributeMaxDynamicSharedMemorySize, GEMM_SMEM);
    cudaFuncSetAttribute(attention_kernel,
                         cudaFuncAttributeMaxDynamicSharedMemorySize, ATT_SMEM);

    // 0) weights fp32 -> bf16
    f2bf_kernel<<<(3*CH*CH/4 + 255)/256, 256>>>(qkv_w, wq, 3*CH*CH);
    f2bf_kernel<<<(CH*CH/4 + 255)/256, 256>>>(proj_w, wp, CH*CH);

    // 1) GroupNorm -> bf16
    groupnorm_kernel<<<BATCH*NGROUPS, 1024>>>(x, gn_w, gn_b, xn);

    // 2) qkv GEMM (bf16 out, q rows pre-scaled by 0.125*log2e)
    mma_gemm_kernel<true><<<dim3(HW_/GBN, (3*CH)/GBM, BATCH), 512, GEMM_SMEM>>>(
        wq, xn, qkvb, qkv_b, (const float*)0, 3*CH, CH, HW_, CH);

    // 3) flash attention (128 queries/block, 4 warps, exp2 softmax)
    attention_kernel<<<dim3(HW_/128, BATCH*NH), 128, ATT_SMEM>>>(qkvb, att);

    // 4) proj GEMM (fp32 out + bias + residual)
    mma_gemm_kernel<false><<<dim3(HW_/GBN, CH/GBM, BATCH), 512, GEMM_SMEM>>>(
        wp, att, out, proj_b, x, CH, CH, HW_, 0);
}